// round 14
// baseline (speedup 1.0000x reference)
#include <cuda_runtime.h>
#include <cuda_fp16.h>
#include <cstdint>
#include <cstddef>

#define SEQ 65536
#define HID 128
#define NG  512
#define INP 64

// x-gate scratch, slot = j*4 + gate (+2 steps padding for prefetch)
static __device__ float g_xg[(size_t)(SEQ + 2) * NG];

union F2U { float2 f; unsigned long long u; };
union H4U { float4 v; __half2 h[4]; };

static __device__ __forceinline__ unsigned long long ld2(const float2* p) {
    F2U u; u.f = *p; return u.u;
}
static __device__ __forceinline__ unsigned long long ffma2(unsigned long long a,
                                                           unsigned long long b,
                                                           unsigned long long c) {
    unsigned long long d;
    asm("fma.rn.f32x2 %0, %1, %2, %3;" : "=l"(d) : "l"(a), "l"(b), "l"(c));
    return d;
}
static __device__ __forceinline__ unsigned long long fadd2(unsigned long long a,
                                                           unsigned long long b) {
    unsigned long long d;
    asm("add.rn.f32x2 %0, %1, %2;" : "=l"(d) : "l"(a), "l"(b));
    return d;
}
static __device__ __forceinline__ float hsum2(unsigned long long a) {
    F2U u; u.u = a; return u.f.x + u.f.y;
}
static __device__ __forceinline__ float ftanh(float x) {
    float y; asm("tanh.approx.f32 %0, %1;" : "=f"(y) : "f"(x)); return y;
}
static __device__ __forceinline__ float fsigm(float x) {
    return fmaf(0.5f, ftanh(0.5f * x), 0.5f);
}

#define MMA(d0, d1, d2, d3, a0, a1, a2, a3, b0, b1)                            \
    asm volatile(                                                              \
        "mma.sync.aligned.m16n8k16.row.col.f32.f16.f16.f32 "                   \
        "{%0,%1,%2,%3}, {%4,%5,%6,%7}, {%8,%9}, {%0,%1,%2,%3};"                \
        : "+f"(d0), "+f"(d1), "+f"(d2), "+f"(d3)                               \
        : "r"(a0), "r"(a1), "r"(a2), "r"(a3), "r"(b0), "r"(b1))

// ---------------------------------------------------------------------------
// Phase 1: x_gates with slot = j*4 + gate  (row r = gate*128 + j)
// ---------------------------------------------------------------------------
__global__ void __launch_bounds__(512, 1)
gemm_xg(const float* __restrict__ x, const float* __restrict__ Wih,
        const float* __restrict__ bih, const float* __restrict__ bhh)
{
    __shared__ __align__(16) float xs[128 * INP];
    const int r  = threadIdx.x;
    const int t0 = blockIdx.x * 128;

    {
        const float4* src = (const float4*)(x + (size_t)t0 * INP);
        float4* dst = (float4*)xs;
        #pragma unroll
        for (int i = r; i < 128 * INP / 4; i += 512) dst[i] = src[i];
    }

    unsigned long long w[32];
    {
        const float2* wr = (const float2*)(Wih + (size_t)r * INP);
        #pragma unroll
        for (int i = 0; i < 32; i++) w[i] = ld2(wr + i);
    }
    const float bias = bih[r] + bhh[r];
    const int slot = (r & 127) * 4 + (r >> 7);
    __syncthreads();

    for (int tt = 0; tt < 128; tt++) {
        const float2* xp = (const float2*)(xs + tt * INP);
        unsigned long long a0 = 0ull, a1 = 0ull, a2 = 0ull, a3 = 0ull;
        #pragma unroll
        for (int i = 0; i < 32; i += 4) {
            a0 = ffma2(w[i + 0], ld2(xp + i + 0), a0);
            a1 = ffma2(w[i + 1], ld2(xp + i + 1), a1);
            a2 = ffma2(w[i + 2], ld2(xp + i + 2), a2);
            a3 = ffma2(w[i + 3], ld2(xp + i + 3), a3);
        }
        g_xg[(size_t)(t0 + tt) * NG + slot] =
            hsum2(fadd2(fadd2(a0, a1), fadd2(a2, a3))) + bias;
    }
}

// ---------------------------------------------------------------------------
// Phase 2+3: single-CTA IN-WARP HYBRID scan, 256 threads / 8 warps.
// Warp w owns columns [16w, 16w+16), all 4 gates (64 rows).
//  - k in [0,64):  16 HMMA m16n8k16 (4 gate M-tiles x 4 K-steps), h in B col0.
//    D lands in lanes kq==0: d[g][0] = col jb+r0, d[g][2] = col jb+r0+8.
//  - k in [64,128): scalar HFMA2. Lane (gl=lane>>3, cp=lane&7) computes rows
//    (gl*128 + jb+cp) and (+8) over the upper k-half -> SMEM scratch.
//  - Combine in holder lanes (kq==0): d + scratch + xg, activations, c/h.
// MMA chains retire under the scalar FMA work -> both pipes busy.
// ---------------------------------------------------------------------------
__global__ void __launch_bounds__(256, 1)
lstm_scan(const float* __restrict__ Whh,
          const float* __restrict__ Wlin,
          const float* __restrict__ blin,
          float* __restrict__ out)
{
    __shared__ __align__(16) __half h_s[2][HID];
    __shared__ __align__(16) float scratch[8][16][4];   // [warp][col16][gate]

    const int tid  = threadIdx.x;
    const int w_id = tid >> 5;
    const int lane = tid & 31;
    // HMMA ids
    const int r0 = lane >> 2;
    const int kq = lane & 3;
    const int jb = w_id * 16;
    const bool holder = (kq == 0);
    // scalar ids
    const int gl = lane >> 3;
    const int cp = lane & 7;

    // HMMA A-fragments for k in [0,64): ha[gate][kstep][4]
    __half2 ha[4][4][4];
    #pragma unroll
    for (int g = 0; g < 4; g++) {
        const float* rA = Whh + (size_t)(g * HID + jb + r0) * HID;
        const float* rB = Whh + (size_t)(g * HID + jb + r0 + 8) * HID;
        #pragma unroll
        for (int kk = 0; kk < 4; kk++) {
            const int c0 = kk * 16 + 2 * kq;
            ha[g][kk][0] = __float22half2_rn(*(const float2*)(rA + c0));
            ha[g][kk][1] = __float22half2_rn(*(const float2*)(rB + c0));
            ha[g][kk][2] = __float22half2_rn(*(const float2*)(rA + c0 + 8));
            ha[g][kk][3] = __float22half2_rn(*(const float2*)(rB + c0 + 8));
        }
    }
    // scalar weights for k in [64,128): rows (gl, jb+cp) and (gl, jb+cp+8)
    __half2 ws0[32], ws1[32];
    {
        const float2* p0 =
            (const float2*)(Whh + (size_t)(gl * HID + jb + cp) * HID + 64);
        const float2* p1 =
            (const float2*)(Whh + (size_t)(gl * HID + jb + cp + 8) * HID + 64);
        #pragma unroll
        for (int i = 0; i < 32; i++) ws0[i] = __float22half2_rn(p0[i]);
        #pragma unroll
        for (int i = 0; i < 32; i++) ws1[i] = __float22half2_rn(p1[i]);
    }

    if (tid < 2 * HID) ((__half*)h_s)[tid] = __float2half_rn(0.0f);

    float cA = 0.0f, cB = 0.0f;
    const float4* xb = (const float4*)g_xg + (jb + r0);
    float4 xA[2], xB[2];
    if (holder) {
        xA[0] = xb[0];        xB[0] = xb[8];
        xA[1] = xb[NG / 4];   xB[1] = xb[NG / 4 + 8];
    }

    __syncthreads();

#define STEP(B)                                                                \
    {                                                                          \
        const __half* hs = h_s[(B) ^ 1];                                       \
        /* tensor half: k in [0,64) */                                         \
        float d[4][4];                                                         \
        _Pragma("unroll")                                                      \
        for (int g = 0; g < 4; g++) {                                          \
            d[g][0] = 0.0f; d[g][1] = 0.0f; d[g][2] = 0.0f; d[g][3] = 0.0f;    \
        }                                                                      \
        _Pragma("unroll")                                                      \
        for (int kk = 0; kk < 4; kk++) {                                       \
            uint32_t b01 = 0u, b23 = 0u;                                       \
            if (lane < 4) {                                                    \
                b01 = *(const uint32_t*)(hs + kk * 16 + 2 * lane);             \
                b23 = *(const uint32_t*)(hs + kk * 16 + 2 * lane + 8);         \
            }                                                                  \
            _Pragma("unroll")                                                  \
            for (int g = 0; g < 4; g++) {                                      \
                MMA(d[g][0], d[g][1], d[g][2], d[g][3],                        \
                    *(const uint32_t*)&ha[g][kk][0],                           \
                    *(const uint32_t*)&ha[g][kk][1],                           \
                    *(const uint32_t*)&ha[g][kk][2],                           \
                    *(const uint32_t*)&ha[g][kk][3],                           \
                    b01, b23);                                                 \
            }                                                                  \
        }                                                                      \
        /* scalar half: k in [64,128) */                                       \
        {                                                                      \
            const float4* hp = (const float4*)(hs + 64);                       \
            __half2 z = __float2half2_rn(0.0f);                                \
            __half2 a00 = z, a01 = z, a10 = z, a11 = z;                        \
            _Pragma("unroll")                                                  \
            for (int i = 0; i < 8; i++) {                                      \
                H4U q; q.v = hp[i];                                            \
                a00 = __hfma2(ws0[4 * i + 0], q.h[0], a00);                    \
                a01 = __hfma2(ws0[4 * i + 1], q.h[1], a01);                    \
                a10 = __hfma2(ws1[4 * i + 0], q.h[0], a10);                    \
                a11 = __hfma2(ws1[4 * i + 1], q.h[1], a11);                    \
                a00 = __hfma2(ws0[4 * i + 2], q.h[2], a00);                    \
                a01 = __hfma2(ws0[4 * i + 3], q.h[3], a01);                    \
                a10 = __hfma2(ws1[4 * i + 2], q.h[2], a10);                    \
                a11 = __hfma2(ws1[4 * i + 3], q.h[3], a11);                    \
            }                                                                  \
            const __half2 t0 = __hadd2(a00, a01);                              \
            const __half2 t1 = __hadd2(a10, a11);                              \
            scratch[w_id][cp][gl]     = __low2float(t0) + __high2float(t0);    \
            scratch[w_id][cp + 8][gl] = __low2float(t1) + __high2float(t1);    \
        }                                                                      \
        __syncwarp();                                                          \
        if (holder) {                                                          \
            const float4 scA = *(const float4*)scratch[w_id][r0];              \
            const float4 scB = *(const float4*)scratch[w_id][r0 + 8];          \
            const float iA = fsigm(d[0][0] + scA.x + xA[B].x);                 \
            const float fA = fsigm(d[1][0] + scA.y + xA[B].y);                 \
            const float gA = ftanh(d[2][0] + scA.z + xA[B].z);                 \
            const float oA = fsigm(d[3][0] + scA.w + xA[B].w);                 \
            const float iB = fsigm(d[0][2] + scB.x + xB[B].x);                 \
            const float fB = fsigm(d[1][2] + scB.y + xB[B].y);                 \
            const float gB = ftanh(d[2][2] + scB.z + xB[B].z);                 \
            const float oB = fsigm(d[3][2] + scB.w + xB[B].w);                 \
            cA = fmaf(fA, cA, iA * gA);                                        \
            cB = fmaf(fB, cB, iB * gB);                                        \
            h_s[B][jb + r0]     = __float2half_rn(oA * ftanh(cA));             \
            h_s[B][jb + r0 + 8] = __float2half_rn(oB * ftanh(cB));             \
            xA[B] = xb[2 * (NG / 4)];                                          \
            xB[B] = xb[2 * (NG / 4) + 8];                                      \
            xb += NG / 4;                                                      \
        }                                                                      \
        __syncthreads();                                                       \
    }

    for (int t = 0; t < SEQ; t += 2) {
        STEP(0)
        STEP(1)
    }

    // h_T in h_s[1]; warp 0 reduces the linear head.
    if (tid < 32) {
        float s = 0.0f;
        #pragma unroll
        for (int m = 0; m < 4; m++)
            s += __half2float(h_s[1][lane + 32 * m]) * Wlin[lane + 32 * m];
        #pragma unroll
        for (int dd = 16; dd > 0; dd >>= 1)
            s += __shfl_xor_sync(0xffffffffu, s, dd);
        if (lane == 0)
            out[0] = fsigm(s + blin[0]);
    }
}

extern "C" void kernel_launch(void* const* d_in, const int* in_sizes, int n_in,
                              void* d_out, int out_size) {
    const float* input = (const float*)d_in[0];
    const float* Wih   = (const float*)d_in[1];
    const float* Whh   = (const float*)d_in[2];
    const float* bih   = (const float*)d_in[3];
    const float* bhh   = (const float*)d_in[4];
    const float* Wlin  = (const float*)d_in[5];
    const float* blin  = (const float*)d_in[6];
    float* out = (float*)d_out;

    gemm_xg<<<SEQ / 128, 512>>>(input, Wih, bih, bhh);
    lstm_scan<<<1, 256>>>(Whh, Wlin, blin, out);
}

// round 15
// speedup vs baseline: 1.0047x; 1.0047x over previous
#include <cuda_runtime.h>
#include <cuda_fp16.h>
#include <cstdint>
#include <cstddef>

#define SEQ 65536
#define HID 128
#define NG  512
#define INP 64

// x-gate scratch, slot = j*4 + gate (+2 steps padding for prefetch)
static __device__ float g_xg[(size_t)(SEQ + 2) * NG];

union F2U { float2 f; unsigned long long u; };
union H4U { float4 v; __half2 h[4]; };

static __device__ __forceinline__ unsigned long long ld2(const float2* p) {
    F2U u; u.f = *p; return u.u;
}
static __device__ __forceinline__ unsigned long long ffma2(unsigned long long a,
                                                           unsigned long long b,
                                                           unsigned long long c) {
    unsigned long long d;
    asm("fma.rn.f32x2 %0, %1, %2, %3;" : "=l"(d) : "l"(a), "l"(b), "l"(c));
    return d;
}
static __device__ __forceinline__ unsigned long long fadd2(unsigned long long a,
                                                           unsigned long long b) {
    unsigned long long d;
    asm("add.rn.f32x2 %0, %1, %2;" : "=l"(d) : "l"(a), "l"(b));
    return d;
}
static __device__ __forceinline__ float hsum2(unsigned long long a) {
    F2U u; u.u = a; return u.f.x + u.f.y;
}
static __device__ __forceinline__ uint32_t smem_u32(const void* p) {
    uint32_t a;
    asm("{ .reg .u64 t; cvta.to.shared.u64 t, %1; cvt.u32.u64 %0, t; }"
        : "=r"(a) : "l"(p));
    return a;
}
static __device__ __forceinline__ float ftanh(float x) {
    float y; asm("tanh.approx.f32 %0, %1;" : "=f"(y) : "f"(x)); return y;
}
static __device__ __forceinline__ float fsigm(float x) {
    return fmaf(0.5f, ftanh(0.5f * x), 0.5f);
}
static __device__ __forceinline__ void mbar_wait(uint32_t mb, uint32_t par) {
    asm volatile(
        "{\n\t.reg .pred P;\n"
        "W_%=:\n\t"
        "mbarrier.try_wait.parity.acquire.cta.shared::cta.b64 P, [%0], %1;\n\t"
        "@!P bra W_%=;\n\t}"
        :: "r"(mb), "r"(par) : "memory");
}
static __device__ __forceinline__ void mbar_rearm(uint32_t mb, uint32_t bytes) {
    asm volatile("mbarrier.arrive.expect_tx.shared.b64 _, [%0], %1;"
                 :: "r"(mb), "r"(bytes) : "memory");
}

// ---------------------------------------------------------------------------
// Phase 1: x_gates with slot = j*4 + gate  (row r = gate*128 + j)
// ---------------------------------------------------------------------------
__global__ void __launch_bounds__(512, 1)
gemm_xg(const float* __restrict__ x, const float* __restrict__ Wih,
        const float* __restrict__ bih, const float* __restrict__ bhh)
{
    __shared__ __align__(16) float xs[128 * INP];
    const int r  = threadIdx.x;
    const int t0 = blockIdx.x * 128;

    {
        const float4* src = (const float4*)(x + (size_t)t0 * INP);
        float4* dst = (float4*)xs;
        #pragma unroll
        for (int i = r; i < 128 * INP / 4; i += 512) dst[i] = src[i];
    }

    unsigned long long w[32];
    {
        const float2* wr = (const float2*)(Wih + (size_t)r * INP);
        #pragma unroll
        for (int i = 0; i < 32; i++) w[i] = ld2(wr + i);
    }
    const float bias = bih[r] + bhh[r];
    const int slot = (r & 127) * 4 + (r >> 7);
    __syncthreads();

    for (int tt = 0; tt < 128; tt++) {
        const float2* xp = (const float2*)(xs + tt * INP);
        unsigned long long a0 = 0ull, a1 = 0ull, a2 = 0ull, a3 = 0ull;
        #pragma unroll
        for (int i = 0; i < 32; i += 4) {
            a0 = ffma2(w[i + 0], ld2(xp + i + 0), a0);
            a1 = ffma2(w[i + 1], ld2(xp + i + 1), a1);
            a2 = ffma2(w[i + 2], ld2(xp + i + 2), a2);
            a3 = ffma2(w[i + 3], ld2(xp + i + 3), a3);
        }
        g_xg[(size_t)(t0 + tt) * NG + slot] =
            hsum2(fadd2(fadd2(a0, a1), fadd2(a2, a3))) + bias;
    }
}

// ---------------------------------------------------------------------------
// Phase 2+3: 2-CTA cluster J-split scan, 256 threads/CTA.
// CTA `rank` owns output columns [64*rank, 64*rank+64) = 256 gate rows.
// Thread (w_id, lane): kq = lane>>3 (k-quarter), jj = lane&7,
//   column j = 64*rank + w_id*8 + jj; all 4 gates of that column.
//   k coverage: own segment  [64*rank + kq*16, +16)  (FMA before the wait)
//               peer segment [64*peer + kq*16, +16)  (FMA after the wait)
// Combine: shfl_xor(8) + shfl_xor(16) per gate. All 4 kq copies compute
// c/h redundantly; kq=0 lanes store h locally; cols packed 4-per-b64 f16 and
// sent via 2 st.async per warp (16 msgs = 128 tx bytes per CTA per step).
// ---------------------------------------------------------------------------
__global__ void __launch_bounds__(256, 1) __cluster_dims__(2, 1, 1)
lstm_scan(const float* __restrict__ Whh,
          const float* __restrict__ Wlin,
          const float* __restrict__ blin,
          float* __restrict__ out)
{
    __shared__ __align__(16) __half h_s[2][HID];
    __shared__ __align__(8)  unsigned long long mbar[2];

    const int tid  = threadIdx.x;
    const int w_id = tid >> 5;
    const int lane = tid & 31;
    const int kq   = lane >> 3;
    const int jj   = lane & 7;

    uint32_t rank;
    asm("mov.u32 %0, %%cluster_ctarank;" : "=r"(rank));
    const uint32_t peer = rank ^ 1u;

    const int j = (int)rank * 64 + w_id * 8 + jj;     // my column
    const int k_own  = (int)rank * 64 + kq * 16;      // own k-segment base
    const int k_peer = (int)peer * 64 + kq * 16;      // peer k-segment base

    // Weights: wreg[g][0..7] = own seg, wreg[g][8..15] = peer seg (half2)
    __half2 wreg[4][16];
    #pragma unroll
    for (int g = 0; g < 4; g++) {
        const float2* row = (const float2*)(Whh + (size_t)(g * HID + j) * HID);
        #pragma unroll
        for (int i = 0; i < 8; i++)
            wreg[g][i] = __float22half2_rn(row[k_own / 2 + i]);
        #pragma unroll
        for (int i = 0; i < 8; i++)
            wreg[g][8 + i] = __float22half2_rn(row[k_peer / 2 + i]);
    }

    if (tid < 2 * HID) ((__half*)h_s)[tid] = __float2half_rn(0.0f);

    const uint32_t mb0 = smem_u32(&mbar[0]);
    const uint32_t mb1 = smem_u32(&mbar[1]);
    if (tid == 0) {
        asm volatile("mbarrier.init.shared.b64 [%0], 1;" :: "r"(mb0) : "memory");
        asm volatile("mbarrier.init.shared.b64 [%0], 1;" :: "r"(mb1) : "memory");
        mbar_rearm(mb0, 128);
        mbar_rearm(mb1, 128);
    }
    // peer addresses: barriers + target slots for packed h (lanes 0 and 4)
    uint32_t pmb[2];
    asm("mapa.shared::cluster.u32 %0, %1, %2;" : "=r"(pmb[0]) : "r"(mb0), "r"(peer));
    asm("mapa.shared::cluster.u32 %0, %1, %2;" : "=r"(pmb[1]) : "r"(mb1), "r"(peer));
    const uint32_t hs_a = smem_u32(&h_s[0][0]);
    const uint32_t slot_b = (uint32_t)(((int)rank * 64 + w_id * 8 + (lane & 4)) * 2);
    uint32_t rh[2];
    asm("mapa.shared::cluster.u32 %0, %1, %2;"
        : "=r"(rh[0]) : "r"(hs_a + slot_b), "r"(peer));
    asm("mapa.shared::cluster.u32 %0, %1, %2;"
        : "=r"(rh[1]) : "r"(hs_a + 256u + slot_b), "r"(peer));

    __syncthreads();
    asm volatile("barrier.cluster.arrive.aligned;" ::: "memory");
    asm volatile("barrier.cluster.wait.aligned;"   ::: "memory");

    float c = 0.0f;
    uint32_t p0 = 0, p1 = 0;
    const float4* xb = (const float4*)g_xg + j;
    float4 xg2[2];
    xg2[0] = xb[0];
    xg2[1] = xb[NG / 4];

#define KS(B, DW)                                                              \
    {                                                                          \
        /* own-segment FMA (local h, ready via BAR) */                         \
        const float4* ho = (const float4*)(h_s[B] + k_own);                    \
        __half2 z = __float2half2_rn(0.0f);                                    \
        __half2 a0[4] = {z, z, z, z};                                          \
        __half2 a1[4] = {z, z, z, z};                                          \
        {                                                                      \
            H4U q0, q1; q0.v = ho[0]; q1.v = ho[1];                            \
            _Pragma("unroll")                                                  \
            for (int g = 0; g < 4; g++) {                                      \
                a0[g] = __hfma2(wreg[g][0], q0.h[0], a0[g]);                   \
                a1[g] = __hfma2(wreg[g][1], q0.h[1], a1[g]);                   \
                a0[g] = __hfma2(wreg[g][2], q0.h[2], a0[g]);                   \
                a1[g] = __hfma2(wreg[g][3], q0.h[3], a1[g]);                   \
                a0[g] = __hfma2(wreg[g][4], q1.h[0], a0[g]);                   \
                a1[g] = __hfma2(wreg[g][5], q1.h[1], a1[g]);                   \
                a0[g] = __hfma2(wreg[g][6], q1.h[2], a0[g]);                   \
                a1[g] = __hfma2(wreg[g][7], q1.h[3], a1[g]);                   \
            }                                                                  \
        }                                                                      \
        if (DW) {                                                              \
            const uint32_t mbc = (B) ? mb1 : mb0;                              \
            mbar_wait(mbc, (B) ? p1 : p0);                                     \
            if (B) p1 ^= 1u; else p0 ^= 1u;                                    \
            if (tid == 0) mbar_rearm(mbc, 128);                                \
        }                                                                      \
        /* peer-segment FMA (arrived via st.async) */                          \
        {                                                                      \
            const float4* hp = (const float4*)(h_s[B] + k_peer);               \
            H4U q0, q1; q0.v = hp[0]; q1.v = hp[1];                            \
            _Pragma("unroll")                                                  \
            for (int g = 0; g < 4; g++) {                                      \
                a0[g] = __hfma2(wreg[g][8],  q0.h[0], a0[g]);                  \
                a1[g] = __hfma2(wreg[g][9],  q0.h[1], a1[g]);                  \
                a0[g] = __hfma2(wreg[g][10], q0.h[2], a0[g]);                  \
                a1[g] = __hfma2(wreg[g][11], q0.h[3], a1[g]);                  \
                a0[g] = __hfma2(wreg[g][12], q1.h[0], a0[g]);                  \
                a1[g] = __hfma2(wreg[g][13], q1.h[1], a1[g]);                  \
                a0[g] = __hfma2(wreg[g][14], q1.h[2], a0[g]);                  \
                a1[g] = __hfma2(wreg[g][15], q1.h[3], a1[g]);                  \
            }                                                                  \
        }                                                                      \
        float part[4];                                                         \
        _Pragma("unroll")                                                      \
        for (int g = 0; g < 4; g++) {                                          \
            const __half2 tt = __hadd2(a0[g], a1[g]);                          \
            part[g] = __low2float(tt) + __high2float(tt);                      \
        }                                                                      \
        _Pragma("unroll")                                                      \
        for (int g = 0; g < 4; g++) {                                          \
            part[g] += __shfl_xor_sync(0xffffffffu, part[g], 8);               \
            part[g] += __shfl_xor_sync(0xffffffffu, part[g], 16);              \
        }                                                                      \
        const float iv = fsigm(part[0] + xg2[B].x);                            \
        const float fv = fsigm(part[1] + xg2[B].y);                            \
        const float gv = ftanh(part[2] + xg2[B].z);                            \
        const float ov = fsigm(part[3] + xg2[B].w);                            \
        xg2[B] = xb[2 * (NG / 4)];                                             \
        xb += NG / 4;                                                          \
        c = fmaf(fv, c, iv * gv);                                              \
        const float hv = ov * ftanh(c);                                        \
        /* pack 4 cols -> b64 and ship; kq=0 lanes store locally */            \
        {                                                                      \
            const uint32_t me = (uint32_t)__half_as_ushort(__float2half_rn(hv));\
            const uint32_t nb1 = __shfl_down_sync(0xffffffffu, me, 1);         \
            const uint32_t b32 = me | (nb1 << 16);                             \
            const uint32_t hi  = __shfl_down_sync(0xffffffffu, b32, 2);        \
            if (lane < 8) {                                                    \
                h_s[(B) ^ 1][j] = __float2half_rn(hv);                         \
                if ((lane & 3) == 0) {                                         \
                    const unsigned long long pk =                              \
                        (unsigned long long)b32 |                              \
                        ((unsigned long long)hi << 32);                        \
                    asm volatile(                                              \
                        "st.async.shared::cluster.mbarrier::complete_tx::bytes.b64 " \
                        "[%0], %1, [%2];"                                      \
                        :: "r"(rh[(B) ^ 1]), "l"(pk), "r"(pmb[(B) ^ 1])        \
                        : "memory");                                           \
                }                                                              \
            }                                                                  \
        }                                                                      \
        __syncthreads();                                                       \
    }

    KS(0, 0)
    KS(1, 1)
    for (int t = 2; t < SEQ; t += 2) {
        KS(0, 1)
        KS(1, 1)
    }

    // Final h(SEQ) lives in buffer 0; peer half arrives via mbar[0].
    mbar_wait(mb0, p0);
    __syncthreads();

    if (rank == 0 && tid < 32) {
        float s = 0.0f;
        #pragma unroll
        for (int m = 0; m < 4; m++)
            s += __half2float(h_s[0][lane + 32 * m]) * Wlin[lane + 32 * m];
        #pragma unroll
        for (int dd = 16; dd > 0; dd >>= 1)
            s += __shfl_xor_sync(0xffffffffu, s, dd);
        if (lane == 0)
            out[0] = fsigm(s + blin[0]);
    }

    asm volatile("barrier.cluster.arrive.aligned;" ::: "memory");
    asm volatile("barrier.cluster.wait.aligned;"   ::: "memory");
}

extern "C" void kernel_launch(void* const* d_in, const int* in_sizes, int n_in,
                              void* d_out, int out_size) {
    const float* input = (const float*)d_in[0];
    const float* Wih   = (const float*)d_in[1];
    const float* Whh   = (const float*)d_in[2];
    const float* bih   = (const float*)d_in[3];
    const float* bhh   = (const float*)d_in[4];
    const float* Wlin  = (const float*)d_in[5];
    const float* blin  = (const float*)d_in[6];
    float* out = (float*)d_out;

    gemm_xg<<<SEQ / 128, 512>>>(input, Wih, bih, bhh);
    lstm_scan<<<2, 256>>>(Whh, Wlin, blin, out);
}

// round 16
// speedup vs baseline: 1.4909x; 1.4840x over previous
#include <cuda_runtime.h>
#include <cuda_fp16.h>
#include <cstdint>
#include <cstddef>

#define SEQ 65536
#define HID 128
#define NG  512
#define INP 64

// x-gate scratch, slot = j*4 + gate (+2 steps padding for prefetch)
static __device__ float g_xg[(size_t)(SEQ + 2) * NG];

union F2U { float2 f; unsigned long long u; };

static __device__ __forceinline__ unsigned long long ld2(const float2* p) {
    F2U u; u.f = *p; return u.u;
}
static __device__ __forceinline__ unsigned long long ffma2(unsigned long long a,
                                                           unsigned long long b,
                                                           unsigned long long c) {
    unsigned long long d;
    asm("fma.rn.f32x2 %0, %1, %2, %3;" : "=l"(d) : "l"(a), "l"(b), "l"(c));
    return d;
}
static __device__ __forceinline__ unsigned long long fadd2(unsigned long long a,
                                                           unsigned long long b) {
    unsigned long long d;
    asm("add.rn.f32x2 %0, %1, %2;" : "=l"(d) : "l"(a), "l"(b));
    return d;
}
static __device__ __forceinline__ float hsum2(unsigned long long a) {
    F2U u; u.u = a; return u.f.x + u.f.y;
}
static __device__ __forceinline__ float ftanh(float x) {
    float y; asm("tanh.approx.f32 %0, %1;" : "=f"(y) : "f"(x)); return y;
}
static __device__ __forceinline__ float fsigm(float x) {
    return fmaf(0.5f, ftanh(0.5f * x), 0.5f);
}
static __device__ __forceinline__ int dp4a(uint32_t a, uint32_t b, int c) {
    int d;
    asm("dp4a.s32.s32 %0, %1, %2, %3;" : "=r"(d) : "r"(a), "r"(b), "r"(c));
    return d;
}
static __device__ __forceinline__ uint32_t pack4(int b0, int b1, int b2, int b3) {
    return (uint32_t)(b0 & 0xff) | ((uint32_t)(b1 & 0xff) << 8) |
           ((uint32_t)(b2 & 0xff) << 16) | ((uint32_t)(b3 & 0xff) << 24);
}

// ---------------------------------------------------------------------------
// Phase 1: x_gates with slot = j*4 + gate  (row r = gate*128 + j)
// ---------------------------------------------------------------------------
__global__ void __launch_bounds__(512, 1)
gemm_xg(const float* __restrict__ x, const float* __restrict__ Wih,
        const float* __restrict__ bih, const float* __restrict__ bhh)
{
    __shared__ __align__(16) float xs[128 * INP];
    const int r  = threadIdx.x;
    const int t0 = blockIdx.x * 128;

    {
        const float4* src = (const float4*)(x + (size_t)t0 * INP);
        float4* dst = (float4*)xs;
        #pragma unroll
        for (int i = r; i < 128 * INP / 4; i += 512) dst[i] = src[i];
    }

    unsigned long long w[32];
    {
        const float2* wr = (const float2*)(Wih + (size_t)r * INP);
        #pragma unroll
        for (int i = 0; i < 32; i++) w[i] = ld2(wr + i);
    }
    const float bias = bih[r] + bhh[r];
    const int slot = (r & 127) * 4 + (r >> 7);
    __syncthreads();

    for (int tt = 0; tt < 128; tt++) {
        const float2* xp = (const float2*)(xs + tt * INP);
        unsigned long long a0 = 0ull, a1 = 0ull, a2 = 0ull, a3 = 0ull;
        #pragma unroll
        for (int i = 0; i < 32; i += 4) {
            a0 = ffma2(w[i + 0], ld2(xp + i + 0), a0);
            a1 = ffma2(w[i + 1], ld2(xp + i + 1), a1);
            a2 = ffma2(w[i + 2], ld2(xp + i + 2), a2);
            a3 = ffma2(w[i + 3], ld2(xp + i + 3), a3);
        }
        g_xg[(size_t)(t0 + tt) * NG + slot] =
            hsum2(fadd2(fadd2(a0, a1), fadd2(a2, a3))) + bias;
    }
}

// ---------------------------------------------------------------------------
// Phase 2+3: single-CTA INT8/DP4A scan, 256 threads.
// Thread (w, lane): kh = lane>>4, jj = lane&15, column j = w*16+jj.
// Owns all 4 gate rows of column j over k in [kh*64, kh*64+64).
// Weights quantized per-row (scale = full-row max/127, maxes combined across
// the kh pair via shfl) into 16 packed-int8 words per row = 64 regs.
// h kept as int8 (scale 127) in SMEM; dp4a accumulates exactly in int32;
// partial int accs combined with ONE integer shfl_xor(16) per gate, then a
// single I2F + scale. All lanes compute c/h redundantly (f32, no divergence);
// kh=0 lanes store quantized h. Final head uses live f32 hv (no int8 error).
// ---------------------------------------------------------------------------
__global__ void __launch_bounds__(256, 1)
lstm_scan(const float* __restrict__ Whh,
          const float* __restrict__ Wlin,
          const float* __restrict__ blin,
          float* __restrict__ out)
{
    __shared__ __align__(16) char h_s[2][HID];
    __shared__ __align__(16) float h_fin[HID];

    const int tid  = threadIdx.x;
    const int w_id = tid >> 5;
    const int lane = tid & 31;
    const int kh   = lane >> 4;          // k-half 0/1
    const int jj   = lane & 15;
    const int j    = w_id * 16 + jj;     // column 0..127

    // ---- quantize weights: wq[g][i] packs W_hh[g*128+j][kh*64+4i .. +4i+3]
    uint32_t wq[4][16];
    float qs[4];
    #pragma unroll
    for (int g = 0; g < 4; g++) {
        const float* row = Whh + (size_t)(g * HID + j) * HID + kh * 64;
        float m = 0.0f;
        #pragma unroll
        for (int k = 0; k < 64; k++) m = fmaxf(m, fabsf(row[k]));
        m = fmaxf(m, __shfl_xor_sync(0xffffffffu, m, 16));
        m = fmaxf(m, 1e-30f);
        qs[g] = m * (1.0f / 16129.0f);          // (m/127) * (1/127)
        const float r127 = 127.0f / m;
        #pragma unroll
        for (int i = 0; i < 16; i++) {
            const int b0 = __float2int_rn(row[4 * i + 0] * r127);
            const int b1 = __float2int_rn(row[4 * i + 1] * r127);
            const int b2 = __float2int_rn(row[4 * i + 2] * r127);
            const int b3 = __float2int_rn(row[4 * i + 3] * r127);
            wq[g][i] = pack4(b0, b1, b2, b3);
        }
    }

    if (tid < 64) ((uint32_t*)h_s)[tid] = 0u;    // zero both int8 h buffers

    float c = 0.0f, hv_last = 0.0f;
    const float4* xb = (const float4*)g_xg + j;  // float4 = 4 gates of col j
    float4 xg2[2];
    xg2[0] = xb[0];
    xg2[1] = xb[NG / 4];

    __syncthreads();

#define STEP(B)                                                                \
    {                                                                          \
        const uint4* hp = (const uint4*)(h_s[(B) ^ 1] + kh * 64);              \
        const uint4 q0 = hp[0], q1 = hp[1], q2 = hp[2], q3 = hp[3];            \
        int ac0 = 0, ac1 = 0, ac2 = 0, ac3 = 0;                                \
        _Pragma("unroll")                                                      \
        for (int g = 0; g < 1; g++) { /* manual 4-gate expansion below */ }    \
        ac0 = dp4a(wq[0][0], q0.x, ac0);  ac1 = dp4a(wq[1][0], q0.x, ac1);     \
        ac2 = dp4a(wq[2][0], q0.x, ac2);  ac3 = dp4a(wq[3][0], q0.x, ac3);     \
        ac0 = dp4a(wq[0][1], q0.y, ac0);  ac1 = dp4a(wq[1][1], q0.y, ac1);     \
        ac2 = dp4a(wq[2][1], q0.y, ac2);  ac3 = dp4a(wq[3][1], q0.y, ac3);     \
        ac0 = dp4a(wq[0][2], q0.z, ac0);  ac1 = dp4a(wq[1][2], q0.z, ac1);     \
        ac2 = dp4a(wq[2][2], q0.z, ac2);  ac3 = dp4a(wq[3][2], q0.z, ac3);     \
        ac0 = dp4a(wq[0][3], q0.w, ac0);  ac1 = dp4a(wq[1][3], q0.w, ac1);     \
        ac2 = dp4a(wq[2][3], q0.w, ac2);  ac3 = dp4a(wq[3][3], q0.w, ac3);     \
        ac0 = dp4a(wq[0][4], q1.x, ac0);  ac1 = dp4a(wq[1][4], q1.x, ac1);     \
        ac2 = dp4a(wq[2][4], q1.x, ac2);  ac3 = dp4a(wq[3][4], q1.x, ac3);     \
        ac0 = dp4a(wq[0][5], q1.y, ac0);  ac1 = dp4a(wq[1][5], q1.y, ac1);     \
        ac2 = dp4a(wq[2][5], q1.y, ac2);  ac3 = dp4a(wq[3][5], q1.y, ac3);     \
        ac0 = dp4a(wq[0][6], q1.z, ac0);  ac1 = dp4a(wq[1][6], q1.z, ac1);     \
        ac2 = dp4a(wq[2][6], q1.z, ac2);  ac3 = dp4a(wq[3][6], q1.z, ac3);     \
        ac0 = dp4a(wq[0][7], q1.w, ac0);  ac1 = dp4a(wq[1][7], q1.w, ac1);     \
        ac2 = dp4a(wq[2][7], q1.w, ac2);  ac3 = dp4a(wq[3][7], q1.w, ac3);     \
        ac0 = dp4a(wq[0][8], q2.x, ac0);  ac1 = dp4a(wq[1][8], q2.x, ac1);     \
        ac2 = dp4a(wq[2][8], q2.x, ac2);  ac3 = dp4a(wq[3][8], q2.x, ac3);     \
        ac0 = dp4a(wq[0][9], q2.y, ac0);  ac1 = dp4a(wq[1][9], q2.y, ac1);     \
        ac2 = dp4a(wq[2][9], q2.y, ac2);  ac3 = dp4a(wq[3][9], q2.y, ac3);     \
        ac0 = dp4a(wq[0][10], q2.z, ac0); ac1 = dp4a(wq[1][10], q2.z, ac1);    \
        ac2 = dp4a(wq[2][10], q2.z, ac2); ac3 = dp4a(wq[3][10], q2.z, ac3);    \
        ac0 = dp4a(wq[0][11], q2.w, ac0); ac1 = dp4a(wq[1][11], q2.w, ac1);    \
        ac2 = dp4a(wq[2][11], q2.w, ac2); ac3 = dp4a(wq[3][11], q2.w, ac3);    \
        ac0 = dp4a(wq[0][12], q3.x, ac0); ac1 = dp4a(wq[1][12], q3.x, ac1);    \
        ac2 = dp4a(wq[2][12], q3.x, ac2); ac3 = dp4a(wq[3][12], q3.x, ac3);    \
        ac0 = dp4a(wq[0][13], q3.y, ac0); ac1 = dp4a(wq[1][13], q3.y, ac1);    \
        ac2 = dp4a(wq[2][13], q3.y, ac2); ac3 = dp4a(wq[3][13], q3.y, ac3);    \
        ac0 = dp4a(wq[0][14], q3.z, ac0); ac1 = dp4a(wq[1][14], q3.z, ac1);    \
        ac2 = dp4a(wq[2][14], q3.z, ac2); ac3 = dp4a(wq[3][14], q3.z, ac3);    \
        ac0 = dp4a(wq[0][15], q3.w, ac0); ac1 = dp4a(wq[1][15], q3.w, ac1);    \
        ac2 = dp4a(wq[2][15], q3.w, ac2); ac3 = dp4a(wq[3][15], q3.w, ac3);    \
        ac0 += __shfl_xor_sync(0xffffffffu, ac0, 16);                          \
        ac1 += __shfl_xor_sync(0xffffffffu, ac1, 16);                          \
        ac2 += __shfl_xor_sync(0xffffffffu, ac2, 16);                          \
        ac3 += __shfl_xor_sync(0xffffffffu, ac3, 16);                          \
        const float s0 = fmaf((float)ac0, qs[0], xg2[B].x);                    \
        const float s1 = fmaf((float)ac1, qs[1], xg2[B].y);                    \
        const float s2 = fmaf((float)ac2, qs[2], xg2[B].z);                    \
        const float s3 = fmaf((float)ac3, qs[3], xg2[B].w);                    \
        xg2[B] = xb[2 * (NG / 4)];                                             \
        xb += NG / 4;                                                          \
        const float iv = fsigm(s0);                                            \
        const float fv = fsigm(s1);                                            \
        const float gv = ftanh(s2);                                            \
        const float ov = fsigm(s3);                                            \
        c = fmaf(fv, c, iv * gv);                                              \
        const float hv = ov * ftanh(c);                                        \
        hv_last = hv;                                                          \
        const int hq = __float2int_rn(hv * 127.0f);                            \
        if (kh == 0) h_s[B][j] = (char)hq;                                     \
        __syncthreads();                                                       \
    }

    for (int t = 0; t < SEQ; t += 2) {
        STEP(0)
        STEP(1)
    }

    // Final head from live f32 h values (no int8 quantization error).
    if (kh == 0) h_fin[j] = hv_last;
    __syncthreads();
    if (tid < 32) {
        float s = 0.0f;
        #pragma unroll
        for (int m = 0; m < 4; m++)
            s += h_fin[lane + 32 * m] * Wlin[lane + 32 * m];
        #pragma unroll
        for (int dd = 16; dd > 0; dd >>= 1)
            s += __shfl_xor_sync(0xffffffffu, s, dd);
        if (lane == 0)
            out[0] = fsigm(s + blin[0]);
    }
}

extern "C" void kernel_launch(void* const* d_in, const int* in_sizes, int n_in,
                              void* d_out, int out_size) {
    const float* input = (const float*)d_in[0];
    const float* Wih   = (const float*)d_in[1];
    const float* Whh   = (const float*)d_in[2];
    const float* bih   = (const float*)d_in[3];
    const float* bhh   = (const float*)d_in[4];
    const float* Wlin  = (const float*)d_in[5];
    const float* blin  = (const float*)d_in[6];
    float* out = (float*)d_out;

    gemm_xg<<<SEQ / 128, 512>>>(input, Wih, bih, bhh);
    lstm_scan<<<1, 256>>>(Whh, Wlin, blin, out);
}

// round 17
// speedup vs baseline: 1.5724x; 1.0547x over previous
#include <cuda_runtime.h>
#include <cuda_fp16.h>
#include <cstdint>
#include <cstddef>

#define SEQ 65536
#define HID 128
#define NG  512
#define INP 64

// x-gate scratch, slot = j*4 + gate (+2 steps padding for prefetch)
static __device__ float g_xg[(size_t)(SEQ + 2) * NG];

union F2U { float2 f; unsigned long long u; };

static __device__ __forceinline__ unsigned long long ld2(const float2* p) {
    F2U u; u.f = *p; return u.u;
}
static __device__ __forceinline__ unsigned long long ffma2(unsigned long long a,
                                                           unsigned long long b,
                                                           unsigned long long c) {
    unsigned long long d;
    asm("fma.rn.f32x2 %0, %1, %2, %3;" : "=l"(d) : "l"(a), "l"(b), "l"(c));
    return d;
}
static __device__ __forceinline__ unsigned long long fadd2(unsigned long long a,
                                                           unsigned long long b) {
    unsigned long long d;
    asm("add.rn.f32x2 %0, %1, %2;" : "=l"(d) : "l"(a), "l"(b));
    return d;
}
static __device__ __forceinline__ float hsum2(unsigned long long a) {
    F2U u; u.u = a; return u.f.x + u.f.y;
}
static __device__ __forceinline__ float ftanh(float x) {
    float y; asm("tanh.approx.f32 %0, %1;" : "=f"(y) : "f"(x)); return y;
}
static __device__ __forceinline__ float fsigm(float x) {
    return fmaf(0.5f, ftanh(0.5f * x), 0.5f);
}
static __device__ __forceinline__ int dp4a(uint32_t a, uint32_t b, int c) {
    int d;
    asm("dp4a.s32.s32 %0, %1, %2, %3;" : "=r"(d) : "r"(a), "r"(b), "r"(c));
    return d;
}
static __device__ __forceinline__ uint32_t pack4(int b0, int b1, int b2, int b3) {
    return (uint32_t)(b0 & 0xff) | ((uint32_t)(b1 & 0xff) << 8) |
           ((uint32_t)(b2 & 0xff) << 16) | ((uint32_t)(b3 & 0xff) << 24);
}

#define MAGIC_I   0x4B400000
#define MAGIC_F   12582912.0f

// ---------------------------------------------------------------------------
// Phase 1: x_gates with slot = j*4 + gate  (row r = gate*128 + j)
// ---------------------------------------------------------------------------
__global__ void __launch_bounds__(512, 1)
gemm_xg(const float* __restrict__ x, const float* __restrict__ Wih,
        const float* __restrict__ bih, const float* __restrict__ bhh)
{
    __shared__ __align__(16) float xs[128 * INP];
    const int r  = threadIdx.x;
    const int t0 = blockIdx.x * 128;

    {
        const float4* src = (const float4*)(x + (size_t)t0 * INP);
        float4* dst = (float4*)xs;
        #pragma unroll
        for (int i = r; i < 128 * INP / 4; i += 512) dst[i] = src[i];
    }

    unsigned long long w[32];
    {
        const float2* wr = (const float2*)(Wih + (size_t)r * INP);
        #pragma unroll
        for (int i = 0; i < 32; i++) w[i] = ld2(wr + i);
    }
    const float bias = bih[r] + bhh[r];
    const int slot = (r & 127) * 4 + (r >> 7);
    __syncthreads();

    for (int tt = 0; tt < 128; tt++) {
        const float2* xp = (const float2*)(xs + tt * INP);
        unsigned long long a0 = 0ull, a1 = 0ull, a2 = 0ull, a3 = 0ull;
        #pragma unroll
        for (int i = 0; i < 32; i += 4) {
            a0 = ffma2(w[i + 0], ld2(xp + i + 0), a0);
            a1 = ffma2(w[i + 1], ld2(xp + i + 1), a1);
            a2 = ffma2(w[i + 2], ld2(xp + i + 2), a2);
            a3 = ffma2(w[i + 3], ld2(xp + i + 3), a3);
        }
        g_xg[(size_t)(t0 + tt) * NG + slot] =
            hsum2(fadd2(fadd2(a0, a1), fadd2(a2, a3))) + bias;
    }
}

// ---------------------------------------------------------------------------
// Phase 2+3: single-CTA INT8/DP4A scan, 128 threads (4 warps).
// Thread = column j (= tid): all 4 gate rows, FULL k in-thread.
//   - weights: per-row int8 quant, 4 x 32 packed words (128 regs)
//   - h: int8[128] in SMEM (scale 127), loaded as 8 uint4 broadcasts
//   - int->float via magic-number (IADD + FFMA); the -MAGIC*qs offset is
//     folded into the xg prefetch, off the critical path
//   - NO shuffles anywhere; one bar.sync per step with 128 threads
// ---------------------------------------------------------------------------
__global__ void __launch_bounds__(128, 1)
lstm_scan(const float* __restrict__ Whh,
          const float* __restrict__ Wlin,
          const float* __restrict__ blin,
          float* __restrict__ out)
{
    __shared__ __align__(16) char h_s[2][HID];
    __shared__ __align__(16) float h_fin[HID];

    const int tid = threadIdx.x;
    const int j   = tid;                 // column 0..127
    const int lane = tid & 31;

    // ---- quantize weights: wq[g][i] packs W_hh[g*128+j][4i .. 4i+3]
    uint32_t wq[4][32];
    float qs[4];
    float4 og;                            // -MAGIC * qs per gate
    #pragma unroll
    for (int g = 0; g < 4; g++) {
        const float* row = Whh + (size_t)(g * HID + j) * HID;
        float m = 0.0f;
        #pragma unroll
        for (int k = 0; k < HID; k++) m = fmaxf(m, fabsf(row[k]));
        m = fmaxf(m, 1e-30f);
        qs[g] = m * (1.0f / 16129.0f);    // (m/127) * (1/127)
        const float r127 = 127.0f / m;
        #pragma unroll
        for (int i = 0; i < 32; i++) {
            const int b0 = __float2int_rn(row[4 * i + 0] * r127);
            const int b1 = __float2int_rn(row[4 * i + 1] * r127);
            const int b2 = __float2int_rn(row[4 * i + 2] * r127);
            const int b3 = __float2int_rn(row[4 * i + 3] * r127);
            wq[g][i] = pack4(b0, b1, b2, b3);
        }
    }
    og.x = -MAGIC_F * qs[0];
    og.y = -MAGIC_F * qs[1];
    og.z = -MAGIC_F * qs[2];
    og.w = -MAGIC_F * qs[3];

    if (tid < 64) ((uint32_t*)h_s)[tid] = 0u;   // zero both int8 h buffers

    float c = 0.0f, hv_last = 0.0f;
    const float4* xb = (const float4*)g_xg + j; // float4 = 4 gates of col j
    float4 xgo[2];
    {
        float4 t0v = xb[0], t1v = xb[NG / 4];
        xgo[0] = make_float4(t0v.x + og.x, t0v.y + og.y, t0v.z + og.z, t0v.w + og.w);
        xgo[1] = make_float4(t1v.x + og.x, t1v.y + og.y, t1v.z + og.z, t1v.w + og.w);
    }

    __syncthreads();

#define STEP(B)                                                                \
    {                                                                          \
        const uint4* hp = (const uint4*)h_s[(B) ^ 1];                          \
        uint32_t hw[32];                                                       \
        _Pragma("unroll")                                                      \
        for (int i = 0; i < 8; i++) {                                          \
            const uint4 q = hp[i];                                             \
            hw[4 * i + 0] = q.x; hw[4 * i + 1] = q.y;                          \
            hw[4 * i + 2] = q.z; hw[4 * i + 3] = q.w;                          \
        }                                                                      \
        int ac0 = 0, ac1 = 0, ac2 = 0, ac3 = 0;                                \
        _Pragma("unroll")                                                      \
        for (int i = 0; i < 32; i++) {                                         \
            ac0 = dp4a(wq[0][i], hw[i], ac0);                                  \
            ac1 = dp4a(wq[1][i], hw[i], ac1);                                  \
            ac2 = dp4a(wq[2][i], hw[i], ac2);                                  \
            ac3 = dp4a(wq[3][i], hw[i], ac3);                                  \
        }                                                                      \
        const float f0 = __int_as_float(ac0 + MAGIC_I);                        \
        const float f1 = __int_as_float(ac1 + MAGIC_I);                        \
        const float f2 = __int_as_float(ac2 + MAGIC_I);                        \
        const float f3 = __int_as_float(ac3 + MAGIC_I);                        \
        const float s0 = fmaf(f0, qs[0], xgo[B].x);                            \
        const float s1 = fmaf(f1, qs[1], xgo[B].y);                            \
        const float s2 = fmaf(f2, qs[2], xgo[B].z);                            \
        const float s3 = fmaf(f3, qs[3], xgo[B].w);                            \
        const float iv = fsigm(s0);                                            \
        const float fv = fsigm(s1);                                            \
        const float gv = ftanh(s2);                                            \
        const float ov = fsigm(s3);                                            \
        c = fmaf(fv, c, iv * gv);                                              \
        const float hv = ov * ftanh(c);                                        \
        hv_last = hv;                                                          \
        h_s[B][j] = (char)__float2int_rn(hv * 127.0f);                         \
        {   /* prefetch + fold offset (off critical path) */                   \
            const float4 xr = xb[2 * (NG / 4)];                                \
            xb += NG / 4;                                                      \
            xgo[B] = make_float4(xr.x + og.x, xr.y + og.y,                     \
                                 xr.z + og.z, xr.w + og.w);                    \
        }                                                                      \
        __syncthreads();                                                       \
    }

    for (int t = 0; t < SEQ; t += 2) {
        STEP(0)
        STEP(1)
    }

    // Final head from live f32 h values (no int8 quantization error).
    h_fin[j] = hv_last;
    __syncthreads();
    if (tid < 32) {
        float s = 0.0f;
        #pragma unroll
        for (int m = 0; m < 4; m++)
            s += h_fin[lane + 32 * m] * Wlin[lane + 32 * m];
        #pragma unroll
        for (int dd = 16; dd > 0; dd >>= 1)
            s += __shfl_xor_sync(0xffffffffu, s, dd);
        if (lane == 0)
            out[0] = fsigm(s + blin[0]);
    }
}

extern "C" void kernel_launch(void* const* d_in, const int* in_sizes, int n_in,
                              void* d_out, int out_size) {
    const float* input = (const float*)d_in[0];
    const float* Wih   = (const float*)d_in[1];
    const float* Whh   = (const float*)d_in[2];
    const float* bih   = (const float*)d_in[3];
    const float* bhh   = (const float*)d_in[4];
    const float* Wlin  = (const float*)d_in[5];
    const float* blin  = (const float*)d_in[6];
    float* out = (float*)d_out;

    gemm_xg<<<SEQ / 128, 512>>>(input, Wih, bih, bhh);
    lstm_scan<<<1, 128>>>(Whh, Wlin, blin, out);
}